// round 7
// baseline (speedup 1.0000x reference)
#include <cuda_runtime.h>

// LSTMAutoencoder: B=4096, T=512, F=8, H=16
// enc LSTM -> hT -> repeat -> dec LSTM -> fused linear
//
// 32 lanes per batch element: lane L owns gate rows L and L+32 of the 64-row
// gate matrix (lanes 0-15: i,g ; lanes 16-31: f,o). Each warp processes CH=2
// independent elements (two interleavable chains). 2048 one-warp blocks ->
// balanced 14-vs-13 blocks/SM on 148 SMs. h broadcast via double-buffered
// smem row (+1 __syncwarp/step); sig(f),sig(o) cross to the c-owning low
// lanes via 2x shfl.xor(16). Matvecs are packed fp32x2 (FFMA2) with even/odd
// tree accumulators (h-chain depth 4). Activation scales (-log2e sigmoid,
// 2*log2e tanh) folded into weights/biases; c kept in 2*log2e domain.

using ull = unsigned long long;

#define Bsz 4096
#define Tsz 512
#define Fsz 8
#define Hsz 16
#define CH 2
#define THREADS 32

#define L2E 1.4426950408889634f

__device__ __forceinline__ void fma2(ull& d, ull a, ull b) {
    asm("fma.rn.f32x2 %0, %1, %2, %0;" : "+l"(d) : "l"(a), "l"(b));
}
__device__ __forceinline__ ull fma2a(ull a, ull b, ull c) {
    ull r; asm("fma.rn.f32x2 %0, %1, %2, %3;" : "=l"(r) : "l"(a), "l"(b), "l"(c)); return r;
}
__device__ __forceinline__ ull mul2(ull a, ull b) {
    ull r; asm("mul.rn.f32x2 %0, %1, %2;" : "=l"(r) : "l"(a), "l"(b)); return r;
}
__device__ __forceinline__ ull add2(ull a, ull b) {
    ull r; asm("add.rn.f32x2 %0, %1, %2;" : "=l"(r) : "l"(a), "l"(b)); return r;
}
__device__ __forceinline__ ull pk(float lo, float hi) {
    ull r; asm("mov.b64 %0, {%1, %2};" : "=l"(r) : "f"(lo), "f"(hi)); return r;
}
__device__ __forceinline__ float redu(ull a) {   // lo + hi
    float lo, hi; asm("mov.b64 {%0, %1}, %2;" : "=f"(lo), "=f"(hi) : "l"(a));
    return lo + hi;
}
__device__ __forceinline__ float ex2f_(float x){ float y; asm("ex2.approx.f32 %0, %1;" : "=f"(y) : "f"(x)); return y; }
__device__ __forceinline__ float rcpf_(float x){ float y; asm("rcp.approx.f32 %0, %1;" : "=f"(y) : "f"(x)); return y; }

__global__ void __launch_bounds__(THREADS, 14)
lstm_ae(const float* __restrict__ x,
        const float* __restrict__ eWih, const float* __restrict__ eWhh,
        const float* __restrict__ eBih, const float* __restrict__ eBhh,
        const float* __restrict__ dWih, const float* __restrict__ dWhh,
        const float* __restrict__ dBih, const float* __restrict__ dBhh,
        const float* __restrict__ oW,  const float* __restrict__ oB,
        float* __restrict__ out)
{
    __shared__ __align__(16) float hbuf[2][CH][Hsz];
    const int L  = threadIdx.x;            // 0..31
    const int rA = L;                      // i-row (L<16) / f-row (L>=16)
    const int rB = L + 32;                 // g-row (L<16) / o-row (L>=16)
    const long b0 = (long)blockIdx.x * CH;

    const float scA = -L2E;
    const float scB = (L < 16) ? 2.0f * L2E : -L2E;
    const ull scApk = pk(scA, scA);
    const ull scBpk = pk(scB, scB);

    // ---------------- encoder weights (pre-scaled, packed; shared by chains)
    ull whhA[8], whhB[8], wihA[4], wihB[4];
    ull biasApk, biasBpk;
    {
        const ull* wa = reinterpret_cast<const ull*>(eWhh + rA * Hsz);
        const ull* wb = reinterpret_cast<const ull*>(eWhh + rB * Hsz);
        #pragma unroll
        for (int p = 0; p < 8; ++p) { whhA[p] = mul2(wa[p], scApk); whhB[p] = mul2(wb[p], scBpk); }
        const ull* ia = reinterpret_cast<const ull*>(eWih + rA * Fsz);
        const ull* ib = reinterpret_cast<const ull*>(eWih + rB * Fsz);
        #pragma unroll
        for (int p = 0; p < 4; ++p) { wihA[p] = mul2(ia[p], scApk); wihB[p] = mul2(ib[p], scBpk); }
        biasApk = pk(scA * (eBih[rA] + eBhh[rA]), 0.0f);
        biasBpk = pk(scB * (eBih[rB] + eBhh[rB]), 0.0f);
    }

    if (L < 16) { hbuf[0][0][L] = 0.0f; hbuf[0][1][L] = 0.0f; }
    __syncwarp();

    const longlong2* px0 = reinterpret_cast<const longlong2*>(x + (b0 + 0) * Tsz * Fsz);
    const longlong2* px1 = reinterpret_cast<const longlong2*>(x + (b0 + 1) * Tsz * Fsz);

    float cs[CH] = {0.0f, 0.0f};

    auto ldx = [](ull d[4], const longlong2* p) {
        longlong2 a = p[0], b2 = p[1];
        d[0] = (ull)a.x; d[1] = (ull)a.y; d[2] = (ull)b2.x; d[3] = (ull)b2.y;
    };

    // gate epilogue shared by enc/dec: from accA/accB pair-sums to new h
    auto gates = [&](ull accA, ull accB, float& c) -> float {
        const float uA = rcpf_(1.0f + ex2f_(redu(accA)));  // sig(i) | sig(f)
        const float uB = rcpf_(1.0f + ex2f_(redu(accB)));  // r2(g)  | sig(o)
        const float fS = __shfl_xor_sync(0xffffffffu, uA, 16);  // sig(f) on low
        const float oS = __shfl_xor_sync(0xffffffffu, uB, 16);  // sig(o) on low
        const float gs = fmaf(uB, -4.0f * L2E, 2.0f * L2E);     // 2L2E*tanh(g)
        c = fmaf(fS, c, uA * gs);
        const float rc = rcpf_(1.0f + ex2f_(c));
        return fmaf(oS * rc, -2.0f, oS);                        // sig(o)*tanh(c)
    };

    // one encoder step for both chains
    auto estep = [&](ull xv[CH][4], int rb) {
        float hh[CH];
        #pragma unroll
        for (int u = 0; u < CH; ++u) {
            ull accA = fma2a(wihA[0], xv[u][0], biasApk);
            ull accB = fma2a(wihB[0], xv[u][0], biasBpk);
            #pragma unroll
            for (int p = 1; p < 4; ++p) { fma2(accA, wihA[p], xv[u][p]); fma2(accB, wihB[p], xv[u][p]); }
            const ull* hr = reinterpret_cast<const ull*>(&hbuf[rb][u][0]);
            ull h0 = hr[0], h1 = hr[1], h2 = hr[2], h3 = hr[3],
                h4 = hr[4], h5 = hr[5], h6 = hr[6], h7 = hr[7];
            ull a2 = mul2(whhA[1], h1), b2 = mul2(whhB[1], h1);
            fma2(accA, whhA[0], h0); fma2(accB, whhB[0], h0);
            fma2(a2, whhA[3], h3);   fma2(b2, whhB[3], h3);
            fma2(accA, whhA[2], h2); fma2(accB, whhB[2], h2);
            fma2(a2, whhA[5], h5);   fma2(b2, whhB[5], h5);
            fma2(accA, whhA[4], h4); fma2(accB, whhB[4], h4);
            fma2(a2, whhA[7], h7);   fma2(b2, whhB[7], h7);
            fma2(accA, whhA[6], h6); fma2(accB, whhB[6], h6);
            hh[u] = gates(add2(accA, a2), add2(accB, b2), cs[u]);
        }
        if (L < 16) { hbuf[rb ^ 1][0][L] = hh[0]; hbuf[rb ^ 1][1][L] = hh[1]; }
        __syncwarp();
    };

    // x pipeline: xv = step t, xn = step t+1
    ull xv[CH][4], xn[CH][4];
    ldx(xv[0], px0); ldx(xv[1], px1);
    ldx(xn[0], px0 + 2); ldx(xn[1], px1 + 2);
    px0 += 4; px1 += 4;

    #pragma unroll 1
    for (int t = 0; t < Tsz; t += 2) {
        estep(xv, 0);
        if (t + 2 < Tsz) { ldx(xv[0], px0); ldx(xv[1], px1); px0 += 2; px1 += 2; }
        estep(xn, 1);
        if (t + 2 < Tsz) { ldx(xn[0], px0); ldx(xn[1], px1); px0 += 2; px1 += 2; }
    }
    // hT for both chains in hbuf[0]

    // ---------------- decoder prep ----------------
    ull xpdA[CH], xpdB[CH];
    {
        const ull* wa = reinterpret_cast<const ull*>(dWih + rA * Hsz);
        const ull* wb = reinterpret_cast<const ull*>(dWih + rB * Hsz);
        const float bA = scA * (dBih[rA] + dBhh[rA]);
        const float bB = scB * (dBih[rB] + dBhh[rB]);
        #pragma unroll
        for (int u = 0; u < CH; ++u) {
            const ull* hr0 = reinterpret_cast<const ull*>(&hbuf[0][u][0]);
            ull aA = pk(bA, 0.0f), aB = pk(bB, 0.0f);
            #pragma unroll
            for (int p = 0; p < 8; ++p) {
                fma2(aA, mul2(wa[p], scApk), hr0[p]);
                fma2(aB, mul2(wb[p], scBpk), hr0[p]);
            }
            xpdA[u] = pk(redu(aA), 0.0f);
            xpdB[u] = pk(redu(aB), 0.0f);
        }
        const ull* ha = reinterpret_cast<const ull*>(dWhh + rA * Hsz);
        const ull* hb = reinterpret_cast<const ull*>(dWhh + rB * Hsz);
        #pragma unroll
        for (int p = 0; p < 8; ++p) { whhA[p] = mul2(ha[p], scApk); whhB[p] = mul2(hb[p], scBpk); }
    }
    // output-linear row for lanes 0..7 (others compute-but-don't-store)
    ull owp[8];
    const int f = L & 7;
    {
        const ull* orow = reinterpret_cast<const ull*>(oW + f * Hsz);
        #pragma unroll
        for (int p = 0; p < 8; ++p) owp[p] = orow[p];
    }
    const ull outbpk = pk(oB[f], 0.0f);

    cs[0] = 0.0f; cs[1] = 0.0f;
    __syncwarp();                 // all lanes done reading hT
    if (L < 16) { hbuf[0][0][L] = 0.0f; hbuf[0][1][L] = 0.0f; }
    __syncwarp();

    float* po[CH];
    po[0] = out + (b0 + 0) * Tsz * Fsz + f;
    po[1] = out + (b0 + 1) * Tsz * Fsz + f;

    // decoder step: reads h_{t-1}; when doOut, emits output row for t-1
    // reusing the same h loads, then computes h_t.
    auto dstep = [&](int rb, bool doOut) {
        float hh[CH];
        #pragma unroll
        for (int u = 0; u < CH; ++u) {
            const ull* hr = reinterpret_cast<const ull*>(&hbuf[rb][u][0]);
            ull h0 = hr[0], h1 = hr[1], h2 = hr[2], h3 = hr[3],
                h4 = hr[4], h5 = hr[5], h6 = hr[6], h7 = hr[7];
            if (doOut) {
                ull oacc = fma2a(owp[0], h0, outbpk);
                fma2(oacc, owp[1], h1); fma2(oacc, owp[2], h2);
                fma2(oacc, owp[3], h3); fma2(oacc, owp[4], h4);
                fma2(oacc, owp[5], h5); fma2(oacc, owp[6], h6);
                fma2(oacc, owp[7], h7);
                if (L < 8) { *po[u] = redu(oacc); }
                po[u] += Fsz;
            }
            ull accA = fma2a(whhA[0], h0, xpdA[u]);
            ull accB = fma2a(whhB[0], h0, xpdB[u]);
            ull a2 = mul2(whhA[1], h1), b2 = mul2(whhB[1], h1);
            fma2(accA, whhA[2], h2); fma2(accB, whhB[2], h2);
            fma2(a2, whhA[3], h3);   fma2(b2, whhB[3], h3);
            fma2(accA, whhA[4], h4); fma2(accB, whhB[4], h4);
            fma2(a2, whhA[5], h5);   fma2(b2, whhB[5], h5);
            fma2(accA, whhA[6], h6); fma2(accB, whhB[6], h6);
            fma2(a2, whhA[7], h7);   fma2(b2, whhB[7], h7);
            hh[u] = gates(add2(accA, a2), add2(accB, b2), cs[u]);
        }
        if (L < 16) { hbuf[rb ^ 1][0][L] = hh[0]; hbuf[rb ^ 1][1][L] = hh[1]; }
        __syncwarp();
    };

    dstep(0, false);   // t=0 (no previous h to emit)
    dstep(1, true);    // t=1, emits row 0
    #pragma unroll 1
    for (int t = 2; t < Tsz; t += 2) {
        dstep(0, true);
        dstep(1, true);
    }
    // emit final row (h_{511} in hbuf[0])
    #pragma unroll
    for (int u = 0; u < CH; ++u) {
        const ull* hr = reinterpret_cast<const ull*>(&hbuf[0][u][0]);
        ull oacc = fma2a(owp[0], hr[0], outbpk);
        #pragma unroll
        for (int p = 1; p < 8; ++p) fma2(oacc, owp[p], hr[p]);
        if (L < 8) { *po[u] = redu(oacc); }
    }
}

extern "C" void kernel_launch(void* const* d_in, const int* in_sizes, int n_in,
                              void* d_out, int out_size) {
    (void)in_sizes; (void)n_in; (void)out_size;
    lstm_ae<<<Bsz / CH, THREADS>>>(
        (const float*)d_in[0],
        (const float*)d_in[1], (const float*)d_in[2],
        (const float*)d_in[3], (const float*)d_in[4],
        (const float*)d_in[5], (const float*)d_in[6],
        (const float*)d_in[7], (const float*)d_in[8],
        (const float*)d_in[9], (const float*)d_in[10],
        (float*)d_out);
}

// round 8
// speedup vs baseline: 1.4435x; 1.4435x over previous
#include <cuda_runtime.h>

// LSTMAutoencoder: B=4096, T=512, F=8, H=16
// enc LSTM -> hT -> repeat -> dec LSTM -> fused linear
//
// R5 structure (best: 446us) + MUFU.TANH activations.
// 16 lanes per batch element (lane j owns hidden unit j / gate rows j,16+j,
// 32+j,48+j). Each lane processes CH=2 independent batch elements. 32-thread
// blocks (2 lane-groups x 2 chains = 4 elements) -> 1024 blocks, balanced
// 7-vs-6 across 148 SMs. h broadcast via double-buffered smem row + one
// __syncwarp per step. Matvecs packed fp32x2 (FFMA2), even/odd tree accums.
// Activations: sigmoid(z) = 0.5 + 0.5*tanh(z/2) with the 1/2 argument scale
// folded into the i/f/o weight rows; g row unscaled; tanh.approx everywhere
// (1 MUFU per activation instead of ex2+rcp). c kept in natural domain.

using ull = unsigned long long;

#define Bsz 4096
#define Tsz 512
#define Fsz 8
#define Hsz 16
#define CH 2
#define GPB 2
#define EPB (GPB * CH)          // 4 elements per block
#define THREADS (GPB * 16)      // 32

__device__ __forceinline__ void fma2(ull& d, ull a, ull b) {
    asm("fma.rn.f32x2 %0, %1, %2, %0;" : "+l"(d) : "l"(a), "l"(b));
}
__device__ __forceinline__ ull fma2a(ull a, ull b, ull c) {
    ull r; asm("fma.rn.f32x2 %0, %1, %2, %3;" : "=l"(r) : "l"(a), "l"(b), "l"(c)); return r;
}
__device__ __forceinline__ ull mul2(ull a, ull b) {
    ull r; asm("mul.rn.f32x2 %0, %1, %2;" : "=l"(r) : "l"(a), "l"(b)); return r;
}
__device__ __forceinline__ ull add2(ull a, ull b) {
    ull r; asm("add.rn.f32x2 %0, %1, %2;" : "=l"(r) : "l"(a), "l"(b)); return r;
}
__device__ __forceinline__ ull pk(float lo, float hi) {
    ull r; asm("mov.b64 %0, {%1, %2};" : "=l"(r) : "f"(lo), "f"(hi)); return r;
}
__device__ __forceinline__ float redu(ull a) {   // lo + hi
    float lo, hi; asm("mov.b64 {%0, %1}, %2;" : "=f"(lo), "=f"(hi) : "l"(a));
    return lo + hi;
}
__device__ __forceinline__ float tanha(float x){
    float y; asm("tanh.approx.f32 %0, %1;" : "=f"(y) : "f"(x)); return y;
}

__global__ void __launch_bounds__(THREADS, 8)
lstm_ae(const float* __restrict__ x,
        const float* __restrict__ eWih, const float* __restrict__ eWhh,
        const float* __restrict__ eBih, const float* __restrict__ eBhh,
        const float* __restrict__ dWih, const float* __restrict__ dWhh,
        const float* __restrict__ dBih, const float* __restrict__ dBhh,
        const float* __restrict__ oW,  const float* __restrict__ oB,
        float* __restrict__ out)
{
    __shared__ __align__(16) float hbuf[2][EPB][Hsz];
    const int j   = threadIdx.x & 15;
    const int grp = threadIdx.x >> 4;      // 0..1
    const int e0  = grp * CH;
    const long b0 = (long)blockIdx.x * EPB + e0;

    // gate scales: i/f/o rows get 1/2 (sigmoid-as-tanh), g row gets 1
    const ull scH = pk(0.5f, 0.5f);

    // ---------------- encoder weights (pre-scaled, packed; shared by chains)
    ull whh[4][8];
    ull wih[4][4];
    ull biaspk[4];
    #pragma unroll
    for (int g = 0; g < 4; ++g) {
        const bool isG = (g == 2);
        const float scf = isG ? 1.0f : 0.5f;
        const int row = g * Hsz + j;
        const ull* wr = reinterpret_cast<const ull*>(eWhh + row * Hsz);
        #pragma unroll
        for (int p = 0; p < 8; ++p) whh[g][p] = isG ? wr[p] : mul2(wr[p], scH);
        const ull* wi = reinterpret_cast<const ull*>(eWih + row * Fsz);
        #pragma unroll
        for (int p = 0; p < 4; ++p) wih[g][p] = isG ? wi[p] : mul2(wi[p], scH);
        biaspk[g] = pk(scf * (eBih[row] + eBhh[row]), 0.0f);
    }

    hbuf[0][e0 + 0][j] = 0.0f;
    hbuf[0][e0 + 1][j] = 0.0f;
    __syncwarp();

    const longlong2* px0 = reinterpret_cast<const longlong2*>(x + (b0 + 0) * Tsz * Fsz);
    const longlong2* px1 = reinterpret_cast<const longlong2*>(x + (b0 + 1) * Tsz * Fsz);

    float cs[CH] = {0.0f, 0.0f};

    auto ldx = [](ull d[4], const longlong2* p) {
        longlong2 a = p[0], b2 = p[1];
        d[0] = (ull)a.x; d[1] = (ull)a.y; d[2] = (ull)b2.x; d[3] = (ull)b2.y;
    };

    // gate epilogue: 4 pre-activations -> new h (5 MUFU.TANH total)
    auto gates = [&](ull a0, ull a1, ull a2, ull a3, float& c) -> float {
        const float ti = tanha(redu(a0));          // tanh(zi/2)
        const float tf = tanha(redu(a1));          // tanh(zf/2)
        const float tg = tanha(redu(a2));          // tanh(zg)
        const float to = tanha(redu(a3));          // tanh(zo/2)
        const float gi = fmaf(ti, 0.5f, 0.5f);
        const float gf = fmaf(tf, 0.5f, 0.5f);
        const float go = fmaf(to, 0.5f, 0.5f);
        c = fmaf(gf, c, gi * tg);
        return go * tanha(c);
    };

    // one encoder step for both chains: x regs already loaded
    auto estep = [&](ull xv[CH][4], int rb) {
        float hh[CH];
        #pragma unroll
        for (int u = 0; u < CH; ++u) {
            ull a0 = fma2a(wih[0][0], xv[u][0], biaspk[0]);
            ull a1 = fma2a(wih[1][0], xv[u][0], biaspk[1]);
            ull a2 = fma2a(wih[2][0], xv[u][0], biaspk[2]);
            ull a3 = fma2a(wih[3][0], xv[u][0], biaspk[3]);
            #pragma unroll
            for (int p = 1; p < 4; ++p) {
                fma2(a0, wih[0][p], xv[u][p]); fma2(a1, wih[1][p], xv[u][p]);
                fma2(a2, wih[2][p], xv[u][p]); fma2(a3, wih[3][p], xv[u][p]);
            }
            const ull* hr = reinterpret_cast<const ull*>(&hbuf[rb][e0 + u][0]);
            ull h0 = hr[0], h1 = hr[1], h2 = hr[2], h3 = hr[3],
                h4 = hr[4], h5 = hr[5], h6 = hr[6], h7 = hr[7];
            // even/odd tree accumulators (h-dependent chain depth 4)
            ull b0a = mul2(whh[0][1], h1), b1a = mul2(whh[1][1], h1),
                b2a = mul2(whh[2][1], h1), b3a = mul2(whh[3][1], h1);
            fma2(a0, whh[0][0], h0); fma2(a1, whh[1][0], h0);
            fma2(a2, whh[2][0], h0); fma2(a3, whh[3][0], h0);
            fma2(b0a, whh[0][3], h3); fma2(b1a, whh[1][3], h3);
            fma2(b2a, whh[2][3], h3); fma2(b3a, whh[3][3], h3);
            fma2(a0, whh[0][2], h2); fma2(a1, whh[1][2], h2);
            fma2(a2, whh[2][2], h2); fma2(a3, whh[3][2], h2);
            fma2(b0a, whh[0][5], h5); fma2(b1a, whh[1][5], h5);
            fma2(b2a, whh[2][5], h5); fma2(b3a, whh[3][5], h5);
            fma2(a0, whh[0][4], h4); fma2(a1, whh[1][4], h4);
            fma2(a2, whh[2][4], h4); fma2(a3, whh[3][4], h4);
            fma2(b0a, whh[0][7], h7); fma2(b1a, whh[1][7], h7);
            fma2(b2a, whh[2][7], h7); fma2(b3a, whh[3][7], h7);
            fma2(a0, whh[0][6], h6); fma2(a1, whh[1][6], h6);
            fma2(a2, whh[2][6], h6); fma2(a3, whh[3][6], h6);
            hh[u] = gates(add2(a0, b0a), add2(a1, b1a),
                          add2(a2, b2a), add2(a3, b3a), cs[u]);
        }
        hbuf[rb ^ 1][e0 + 0][j] = hh[0];
        hbuf[rb ^ 1][e0 + 1][j] = hh[1];
        __syncwarp();
    };

    // x pipeline: xv = step t, xn = step t+1
    ull xv[CH][4], xn[CH][4];
    ldx(xv[0], px0); ldx(xv[1], px1);
    ldx(xn[0], px0 + 2); ldx(xn[1], px1 + 2);
    px0 += 4; px1 += 4;

    #pragma unroll 1
    for (int t = 0; t < Tsz; t += 2) {
        estep(xv, 0);
        if (t + 2 < Tsz) { ldx(xv[0], px0); ldx(xv[1], px1); px0 += 2; px1 += 2; }
        estep(xn, 1);
        if (t + 2 < Tsz) { ldx(xn[0], px0); ldx(xn[1], px1); px0 += 2; px1 += 2; }
    }
    // hT for both chains in hbuf[0]

    // ---------------- decoder prep ----------------
    ull xpdpk[CH][4];
    #pragma unroll
    for (int g = 0; g < 4; ++g) {
        const bool isG = (g == 2);
        const float scf = isG ? 1.0f : 0.5f;
        const int row = g * Hsz + j;
        const float bsum = scf * (dBih[row] + dBhh[row]);
        const ull* wr = reinterpret_cast<const ull*>(dWih + row * Hsz);
        #pragma unroll
        for (int u = 0; u < CH; ++u) {
            const ull* hr0 = reinterpret_cast<const ull*>(&hbuf[0][e0 + u][0]);
            ull acc = pk(bsum, 0.0f);
            #pragma unroll
            for (int p = 0; p < 8; ++p) {
                ull w = isG ? wr[p] : mul2(wr[p], scH);
                fma2(acc, w, hr0[p]);
            }
            xpdpk[u][g] = pk(redu(acc), 0.0f);
        }
        const ull* wh = reinterpret_cast<const ull*>(dWhh + row * Hsz);
        #pragma unroll
        for (int p = 0; p < 8; ++p) whh[g][p] = isG ? wh[p] : mul2(wh[p], scH);
    }
    ull owp[8];
    const int f = j & 7;
    {
        const ull* orow = reinterpret_cast<const ull*>(oW + f * Hsz);
        #pragma unroll
        for (int p = 0; p < 8; ++p) owp[p] = orow[p];
    }
    const ull outbpk = pk(oB[f], 0.0f);

    cs[0] = 0.0f; cs[1] = 0.0f;
    __syncwarp();                 // all lanes done reading hT
    hbuf[0][e0 + 0][j] = 0.0f;
    hbuf[0][e0 + 1][j] = 0.0f;
    __syncwarp();

    float* po[CH];
    po[0] = out + (b0 + 0) * Tsz * Fsz + f;
    po[1] = out + (b0 + 1) * Tsz * Fsz + f;

    // decoder step: reads h_{t-1}; when doOut, emits output row for t-1
    // reusing the same h loads, then computes h_t.
    auto dstep = [&](int rb, bool doOut) {
        float hh[CH];
        #pragma unroll
        for (int u = 0; u < CH; ++u) {
            const ull* hr = reinterpret_cast<const ull*>(&hbuf[rb][e0 + u][0]);
            ull h0 = hr[0], h1 = hr[1], h2 = hr[2], h3 = hr[3],
                h4 = hr[4], h5 = hr[5], h6 = hr[6], h7 = hr[7];
            if (doOut) {
                ull oacc = fma2a(owp[0], h0, outbpk);
                fma2(oacc, owp[1], h1); fma2(oacc, owp[2], h2);
                fma2(oacc, owp[3], h3); fma2(oacc, owp[4], h4);
                fma2(oacc, owp[5], h5); fma2(oacc, owp[6], h6);
                fma2(oacc, owp[7], h7);
                if (j < 8) { *po[u] = redu(oacc); }
                po[u] += Fsz;
            }
            ull a0 = fma2a(whh[0][0], h0, xpdpk[u][0]);
            ull a1 = fma2a(whh[1][0], h0, xpdpk[u][1]);
            ull a2 = fma2a(whh[2][0], h0, xpdpk[u][2]);
            ull a3 = fma2a(whh[3][0], h0, xpdpk[u][3]);
            ull b0a = mul2(whh[0][1], h1), b1a = mul2(whh[1][1], h1),
                b2a = mul2(whh[2][1], h1), b3a = mul2(whh[3][1], h1);
            fma2(a0, whh[0][2], h2); fma2(a1, whh[1][2], h2);
            fma2(a2, whh[2][2], h2); fma2(a3, whh[3][2], h2);
            fma2(b0a, whh[0][3], h3); fma2(b1a, whh[1][3], h3);
            fma2(b2a, whh[2][3], h3); fma2(b3a, whh[3][3], h3);
            fma2(a0, whh[0][4], h4); fma2(a1, whh[1][4], h4);
            fma2(a2, whh[2][4], h4); fma2(a3, whh[3][4], h4);
            fma2(b0a, whh[0][5], h5); fma2(b1a, whh[1][5], h5);
            fma2(b2a, whh[2][5], h5); fma2(b3a, whh[3][5], h5);
            fma2(a0, whh[0][6], h6); fma2(a1, whh[1][6], h6);
            fma2(a2, whh[2][6], h6); fma2(a3, whh[3][6], h6);
            fma2(b0a, whh[0][7], h7); fma2(b1a, whh[1][7], h7);
            fma2(b2a, whh[2][7], h7); fma2(b3a, whh[3][7], h7);
            hh[u] = gates(add2(a0, b0a), add2(a1, b1a),
                          add2(a2, b2a), add2(a3, b3a), cs[u]);
        }
        hbuf[rb ^ 1][e0 + 0][j] = hh[0];
        hbuf[rb ^ 1][e0 + 1][j] = hh[1];
        __syncwarp();
    };

    dstep(0, false);   // t=0 (no previous h to emit)
    dstep(1, true);    // t=1, emits row 0
    #pragma unroll 1
    for (int t = 2; t < Tsz; t += 2) {
        dstep(0, true);
        dstep(1, true);
    }
    // emit final row (h_{511} in hbuf[0])
    #pragma unroll
    for (int u = 0; u < CH; ++u) {
        const ull* hr = reinterpret_cast<const ull*>(&hbuf[0][e0 + u][0]);
        ull oacc = fma2a(owp[0], hr[0], outbpk);
        #pragma unroll
        for (int p = 1; p < 8; ++p) fma2(oacc, owp[p], hr[p]);
        if (j < 8) { *po[u] = redu(oacc); }
    }
}

extern "C" void kernel_launch(void* const* d_in, const int* in_sizes, int n_in,
                              void* d_out, int out_size) {
    (void)in_sizes; (void)n_in; (void)out_size;
    lstm_ae<<<Bsz / EPB, THREADS>>>(
        (const float*)d_in[0],
        (const float*)d_in[1], (const float*)d_in[2],
        (const float*)d_in[3], (const float*)d_in[4],
        (const float*)d_in[5], (const float*)d_in[6],
        (const float*)d_in[7], (const float*)d_in[8],
        (const float*)d_in[9], (const float*)d_in[10],
        (float*)d_out);
}

// round 11
// speedup vs baseline: 1.4443x; 1.0005x over previous
#include <cuda_runtime.h>

// LSTMAutoencoder: B=4096, T=512, F=8, H=16
// enc LSTM -> hT -> repeat -> dec LSTM -> fused linear
//
// R8 math (tanh.approx activations, sigmoid(z)=0.5+0.5*tanh(z/2) with the
// 1/2 folded into i/f/o weight rows) + CH=4 chains per lane-group.
// 16 lanes per element; 2 lane-groups x 4 chains = 8 elements per 32-thread
// block -> 512 single-warp blocks: every warp gets its own SMSP (512 < 592),
// so there is no wave tail and all latency hiding comes from 4-way in-warp
// ILP. h exchanged via double-buffered smem row (2x LDS.128 per chain) +
// one __syncwarp per step. Matvecs packed fp32x2 (FFMA2), plain 8-deep
// accumulator chains (16 independent chains per warp-step give the ILP).

using ull = unsigned long long;

#define Bsz 4096
#define Tsz 512
#define Fsz 8
#define Hsz 16
#define CH 4
#define GPB 2
#define EPB (GPB * CH)          // 8 elements per block
#define THREADS (GPB * 16)      // 32

__device__ __forceinline__ void fma2(ull& d, ull a, ull b) {
    asm("fma.rn.f32x2 %0, %1, %2, %0;" : "+l"(d) : "l"(a), "l"(b));
}
__device__ __forceinline__ ull fma2a(ull a, ull b, ull c) {
    ull r; asm("fma.rn.f32x2 %0, %1, %2, %3;" : "=l"(r) : "l"(a), "l"(b), "l"(c)); return r;
}
__device__ __forceinline__ ull mul2(ull a, ull b) {
    ull r; asm("mul.rn.f32x2 %0, %1, %2;" : "=l"(r) : "l"(a), "l"(b)); return r;
}
__device__ __forceinline__ ull pk(float lo, float hi) {
    ull r; asm("mov.b64 %0, {%1, %2};" : "=l"(r) : "f"(lo), "f"(hi)); return r;
}
__device__ __forceinline__ float redu(ull a) {   // lo + hi
    float lo, hi; asm("mov.b64 {%0, %1}, %2;" : "=f"(lo), "=f"(hi) : "l"(a));
    return lo + hi;
}
__device__ __forceinline__ float tanha(float x){
    float y; asm("tanh.approx.f32 %0, %1;" : "=f"(y) : "f"(x)); return y;
}

__global__ void __launch_bounds__(THREADS, 4)
lstm_ae(const float* __restrict__ x,
        const float* __restrict__ eWih, const float* __restrict__ eWhh,
        const float* __restrict__ eBih, const float* __restrict__ eBhh,
        const float* __restrict__ dWih, const float* __restrict__ dWhh,
        const float* __restrict__ dBih, const float* __restrict__ dBhh,
        const float* __restrict__ oW,  const float* __restrict__ oB,
        float* __restrict__ out)
{
    __shared__ __align__(16) float hbuf[2][EPB][Hsz];
    const int j   = threadIdx.x & 15;
    const int grp = threadIdx.x >> 4;      // 0..1
    const int e0  = grp * CH;
    const long b0 = (long)blockIdx.x * EPB + e0;

    const ull scH = pk(0.5f, 0.5f);        // sigmoid-as-tanh arg scale

    // ---------------- encoder weights (pre-scaled, packed; shared by chains)
    ull whh[4][8];
    ull wih[4][4];
    ull biaspk[4];
    #pragma unroll
    for (int g = 0; g < 4; ++g) {
        const bool isG = (g == 2);
        const float scf = isG ? 1.0f : 0.5f;
        const int row = g * Hsz + j;
        const ull* wr = reinterpret_cast<const ull*>(eWhh + row * Hsz);
        #pragma unroll
        for (int p = 0; p < 8; ++p) whh[g][p] = isG ? wr[p] : mul2(wr[p], scH);
        const ull* wi = reinterpret_cast<const ull*>(eWih + row * Fsz);
        #pragma unroll
        for (int p = 0; p < 4; ++p) wih[g][p] = isG ? wi[p] : mul2(wi[p], scH);
        biaspk[g] = pk(scf * (eBih[row] + eBhh[row]), 0.0f);
    }

    #pragma unroll
    for (int u = 0; u < CH; ++u) hbuf[0][e0 + u][j] = 0.0f;
    __syncwarp();

    // single base pointer; chains at immediate offsets u*Tsz*Fsz/2 ll2-units
    const longlong2* px = reinterpret_cast<const longlong2*>(x + b0 * Tsz * Fsz);
    #define XSTRIDE (Tsz * Fsz / 4)        // longlong2 units per element

    float cs[CH] = {0.0f, 0.0f, 0.0f, 0.0f};

    auto ldx = [&](ull d[CH][4], int toff) {
        #pragma unroll
        for (int u = 0; u < CH; ++u) {
            longlong2 a = px[u * XSTRIDE + toff], b2 = px[u * XSTRIDE + toff + 1];
            d[u][0] = (ull)a.x; d[u][1] = (ull)a.y;
            d[u][2] = (ull)b2.x; d[u][3] = (ull)b2.y;
        }
    };

    // gate epilogue: 4 pre-activations -> new h (5 MUFU.TANH)
    auto gates = [&](ull a0, ull a1, ull a2, ull a3, float& c) -> float {
        const float ti = tanha(redu(a0));
        const float tf = tanha(redu(a1));
        const float tg = tanha(redu(a2));
        const float to = tanha(redu(a3));
        const float gi = fmaf(ti, 0.5f, 0.5f);
        const float gf = fmaf(tf, 0.5f, 0.5f);
        const float go = fmaf(to, 0.5f, 0.5f);
        c = fmaf(gf, c, gi * tg);
        return go * tanha(c);
    };

    // one encoder step for all chains
    auto estep = [&](ull xv[CH][4], int rb) {
        float hh[CH];
        #pragma unroll
        for (int u = 0; u < CH; ++u) {
            ull a0 = fma2a(wih[0][0], xv[u][0], biaspk[0]);
            ull a1 = fma2a(wih[1][0], xv[u][0], biaspk[1]);
            ull a2 = fma2a(wih[2][0], xv[u][0], biaspk[2]);
            ull a3 = fma2a(wih[3][0], xv[u][0], biaspk[3]);
            #pragma unroll
            for (int p = 1; p < 4; ++p) {
                fma2(a0, wih[0][p], xv[u][p]); fma2(a1, wih[1][p], xv[u][p]);
                fma2(a2, wih[2][p], xv[u][p]); fma2(a3, wih[3][p], xv[u][p]);
            }
            const longlong2* hr = reinterpret_cast<const longlong2*>(&hbuf[rb][e0 + u][0]);
            longlong2 H0 = hr[0], H1 = hr[1], H2 = hr[2], H3 = hr[3];
            ull h[8] = {(ull)H0.x, (ull)H0.y, (ull)H1.x, (ull)H1.y,
                        (ull)H2.x, (ull)H2.y, (ull)H3.x, (ull)H3.y};
            #pragma unroll
            for (int p = 0; p < 8; ++p) {
                fma2(a0, whh[0][p], h[p]); fma2(a1, whh[1][p], h[p]);
                fma2(a2, whh[2][p], h[p]); fma2(a3, whh[3][p], h[p]);
            }
            hh[u] = gates(a0, a1, a2, a3, cs[u]);
        }
        #pragma unroll
        for (int u = 0; u < CH; ++u) hbuf[rb ^ 1][e0 + u][j] = hh[u];
        __syncwarp();
    };

    // x pipeline: xv = step t, xn = step t+1 (each reloaded 2 steps ahead)
    ull xv[CH][4], xn[CH][4];
    ldx(xv, 0);
    ldx(xn, 2);

    #pragma unroll 1
    for (int t = 0; t < Tsz; t += 2) {
        estep(xv, 0);
        if (t + 2 < Tsz) ldx(xv, (t + 2) * 2);
        estep(xn, 1);
        if (t + 3 < Tsz) ldx(xn, (t + 3) * 2);
    }
    // hT for all chains in hbuf[0]

    // ---------------- decoder prep ----------------
    ull xpdpk[CH][4];
    #pragma unroll
    for (int g = 0; g < 4; ++g) {
        const bool isG = (g == 2);
        const float scf = isG ? 1.0f : 0.5f;
        const int row = g * Hsz + j;
        const float bsum = scf * (dBih[row] + dBhh[row]);
        const ull* wr = reinterpret_cast<const ull*>(dWih + row * Hsz);
        #pragma unroll
        for (int u = 0; u < CH; ++u) {
            const ull* hr0 = reinterpret_cast<const ull*>(&hbuf[0][e0 + u][0]);
            ull acc = pk(bsum, 0.0f);
            #pragma unroll
            for (int p = 0; p < 8; ++p) {
                ull w = isG ? wr[p] : mul2(wr[p], scH);
                fma2(acc, w, hr0[p]);
            }
            xpdpk[u][g] = pk(redu(acc), 0.0f);
        }
        const ull* wh = reinterpret_cast<const ull*>(dWhh + row * Hsz);
        #pragma unroll
        for (int p = 0; p < 8; ++p) whh[g][p] = isG ? wh[p] : mul2(wh[p], scH);
    }
    ull owp[8];
    const int f = j & 7;
    {
        const ull* orow = reinterpret_cast<const ull*>(oW + f * Hsz);
        #pragma unroll
        for (int p = 0; p < 8; ++p) owp[p] = orow[p];
    }
    const ull outbpk = pk(oB[f], 0.0f);

    #pragma unroll
    for (int u = 0; u < CH; ++u) cs[u] = 0.0f;
    __syncwarp();                 // all lanes done reading hT
    #pragma unroll
    for (int u = 0; u < CH; ++u) hbuf[0][e0 + u][j] = 0.0f;
    __syncwarp();

    float* po = out + b0 * Tsz * Fsz + f;   // chain u at po[u*Tsz*Fsz]
    #define OSTRIDE (Tsz * Fsz)

    // decoder step: reads h_{t-1}; when doOut, emits output row for t-1
    // reusing the same h loads, then computes h_t.
    auto dstep = [&](int rb, bool doOut) {
        float hh[CH];
        #pragma unroll
        for (int u = 0; u < CH; ++u) {
            const longlong2* hr = reinterpret_cast<const longlong2*>(&hbuf[rb][e0 + u][0]);
            longlong2 H0 = hr[0], H1 = hr[1], H2 = hr[2], H3 = hr[3];
            ull h[8] = {(ull)H0.x, (ull)H0.y, (ull)H1.x, (ull)H1.y,
                        (ull)H2.x, (ull)H2.y, (ull)H3.x, (ull)H3.y};
            if (doOut) {
                ull oacc = fma2a(owp[0], h[0], outbpk);
                #pragma unroll
                for (int p = 1; p < 8; ++p) fma2(oacc, owp[p], h[p]);
                if (j < 8) po[u * OSTRIDE] = redu(oacc);
            }
            ull a0 = fma2a(whh[0][0], h[0], xpdpk[u][0]);
            ull a1 = fma2a(whh[1][0], h[0], xpdpk[u][1]);
            ull a2 = fma2a(whh[2][0], h[0], xpdpk[u][2]);
            ull a3 = fma2a(whh[3][0], h[0], xpdpk[u][3]);
            #pragma unroll
            for (int p = 1; p < 8; ++p) {
                fma2(a0, whh[0][p], h[p]); fma2(a1, whh[1][p], h[p]);
                fma2(a2, whh[2][p], h[p]); fma2(a3, whh[3][p], h[p]);
            }
            hh[u] = gates(a0, a1, a2, a3, cs[u]);
        }
        if (doOut) po += Fsz;
        #pragma unroll
        for (int u = 0; u < CH; ++u) hbuf[rb ^ 1][e0 + u][j] = hh[u];
        __syncwarp();
    };

    dstep(0, false);   // t=0 (no previous h to emit)
    dstep(1, true);    // t=1, emits row 0
    #pragma unroll 1
    for (int t = 2; t < Tsz; t += 2) {
        dstep(0, true);
        dstep(1, true);
    }
    // emit final row (h_{511} in hbuf[0])
    #pragma unroll
    for (int u = 0; u < CH; ++u) {
        const ull* hr = reinterpret_cast<const ull*>(&hbuf[0][e0 + u][0]);
        ull oacc = fma2a(owp[0], hr[0], outbpk);
        #pragma unroll
        for (int p = 1; p < 8; ++p) fma2(oacc, owp[p], hr[p]);
        if (j < 8) po[u * OSTRIDE] = redu(oacc);
    }
}

extern "C" void kernel_launch(void* const* d_in, const int* in_sizes, int n_in,
                              void* d_out, int out_size) {
    (void)in_sizes; (void)n_in; (void)out_size;
    lstm_ae<<<Bsz / EPB, THREADS>>>(
        (const float*)d_in[0],
        (const float*)d_in[1], (const float*)d_in[2],
        (const float*)d_in[3], (const float*)d_in[4],
        (const float*)d_in[5], (const float*)d_in[6],
        (const float*)d_in[7], (const float*)d_in[8],
        (const float*)d_in[9], (const float*)d_in[10],
        (float*)d_out);
}

// round 12
// speedup vs baseline: 1.5320x; 1.0607x over previous
#include <cuda_runtime.h>

// LSTMAutoencoder: B=4096, T=512, F=8, H=16
// enc LSTM -> hT -> repeat -> dec LSTM -> fused linear
//
// R8 config (best tied at 377us): 16 lanes/element, CH=2 chains per lane
// group, 32-thread blocks, 1024 single-warp blocks; tanh.approx activations
// (sigmoid(z)=0.5+0.5*tanh(z/2), 1/2 folded into i/f/o weight rows).
// R12 changes:
//  - encoder x-projection software-pipelined ONE STEP AHEAD: xproj(t+2) is
//    pure FFMA work placed between the STS and the __syncwarp of step t,
//    filling the MUFU epilogue tail that ptxas cannot cover across the
//    barrier. The h-dependent accumulators seed from the precomputed xp.
//  - even/odd tree accumulators: h-dependent FFMA2 chain depth 4 (was 12).

using ull = unsigned long long;

#define Bsz 4096
#define Tsz 512
#define Fsz 8
#define Hsz 16
#define CH 2
#define GPB 2
#define EPB (GPB * CH)          // 4 elements per block
#define THREADS (GPB * 16)      // 32
#define XSTRIDE (Tsz * Fsz / 4) // longlong2 units per element

__device__ __forceinline__ void fma2(ull& d, ull a, ull b) {
    asm("fma.rn.f32x2 %0, %1, %2, %0;" : "+l"(d) : "l"(a), "l"(b));
}
__device__ __forceinline__ ull fma2a(ull a, ull b, ull c) {
    ull r; asm("fma.rn.f32x2 %0, %1, %2, %3;" : "=l"(r) : "l"(a), "l"(b), "l"(c)); return r;
}
__device__ __forceinline__ ull mul2(ull a, ull b) {
    ull r; asm("mul.rn.f32x2 %0, %1, %2;" : "=l"(r) : "l"(a), "l"(b)); return r;
}
__device__ __forceinline__ ull add2(ull a, ull b) {
    ull r; asm("add.rn.f32x2 %0, %1, %2;" : "=l"(r) : "l"(a), "l"(b)); return r;
}
__device__ __forceinline__ ull pk(float lo, float hi) {
    ull r; asm("mov.b64 %0, {%1, %2};" : "=l"(r) : "f"(lo), "f"(hi)); return r;
}
__device__ __forceinline__ float redu(ull a) {   // lo + hi
    float lo, hi; asm("mov.b64 {%0, %1}, %2;" : "=f"(lo), "=f"(hi) : "l"(a));
    return lo + hi;
}
__device__ __forceinline__ float tanha(float x){
    float y; asm("tanh.approx.f32 %0, %1;" : "=f"(y) : "f"(x)); return y;
}

__global__ void __launch_bounds__(THREADS, 8)
lstm_ae(const float* __restrict__ x,
        const float* __restrict__ eWih, const float* __restrict__ eWhh,
        const float* __restrict__ eBih, const float* __restrict__ eBhh,
        const float* __restrict__ dWih, const float* __restrict__ dWhh,
        const float* __restrict__ dBih, const float* __restrict__ dBhh,
        const float* __restrict__ oW,  const float* __restrict__ oB,
        float* __restrict__ out)
{
    __shared__ __align__(16) float hbuf[2][EPB][Hsz];
    const int j   = threadIdx.x & 15;
    const int grp = threadIdx.x >> 4;      // 0..1
    const int e0  = grp * CH;
    const long b0 = (long)blockIdx.x * EPB + e0;

    const ull scH = pk(0.5f, 0.5f);        // sigmoid-as-tanh arg scale

    // ---------------- encoder weights (pre-scaled, packed; shared by chains)
    ull whh[4][8];
    ull wih[4][4];
    ull biaspk[4];
    #pragma unroll
    for (int g = 0; g < 4; ++g) {
        const bool isG = (g == 2);
        const float scf = isG ? 1.0f : 0.5f;
        const int row = g * Hsz + j;
        const ull* wr = reinterpret_cast<const ull*>(eWhh + row * Hsz);
        #pragma unroll
        for (int p = 0; p < 8; ++p) whh[g][p] = isG ? wr[p] : mul2(wr[p], scH);
        const ull* wi = reinterpret_cast<const ull*>(eWih + row * Fsz);
        #pragma unroll
        for (int p = 0; p < 4; ++p) wih[g][p] = isG ? wi[p] : mul2(wi[p], scH);
        biaspk[g] = pk(scf * (eBih[row] + eBhh[row]), 0.0f);
    }

    #pragma unroll
    for (int u = 0; u < CH; ++u) hbuf[0][e0 + u][j] = 0.0f;
    __syncwarp();

    const longlong2* px = reinterpret_cast<const longlong2*>(x + b0 * Tsz * Fsz);
    float cs[CH] = {0.0f, 0.0f};

    // load x(t) for all chains into regs
    auto ldx = [&](ull d[CH][4], int t) {
        #pragma unroll
        for (int u = 0; u < CH; ++u) {
            longlong2 a = px[u * XSTRIDE + 2 * t], b2 = px[u * XSTRIDE + 2 * t + 1];
            d[u][0] = (ull)a.x; d[u][1] = (ull)a.y;
            d[u][2] = (ull)b2.x; d[u][3] = (ull)b2.y;
        }
    };

    // x-projection: xp[u][g] = bias_g + Wih_g . x_u   (pure FFMA, h-free)
    auto xproj = [&](ull xp[CH][4], ull xv[CH][4]) {
        #pragma unroll
        for (int u = 0; u < CH; ++u) {
            #pragma unroll
            for (int g = 0; g < 4; ++g) {
                ull a = fma2a(wih[g][0], xv[u][0], biaspk[g]);
                fma2(a, wih[g][1], xv[u][1]);
                fma2(a, wih[g][2], xv[u][2]);
                fma2(a, wih[g][3], xv[u][3]);
                xp[u][g] = a;
            }
        }
    };

    // gate epilogue: 4 pre-activations -> new h (5 MUFU.TANH)
    auto gates = [&](ull a0, ull a1, ull a2, ull a3, float& c) -> float {
        const float ti = tanha(redu(a0));
        const float tf = tanha(redu(a1));
        const float tg = tanha(redu(a2));
        const float to = tanha(redu(a3));
        const float gi = fmaf(ti, 0.5f, 0.5f);
        const float gf = fmaf(tf, 0.5f, 0.5f);
        const float go = fmaf(to, 0.5f, 0.5f);
        c = fmaf(gf, c, gi * tg);
        return go * tanha(c);
    };

    // encoder step: consumes xp (projection of x(t)); after storing h and
    // BEFORE the barrier, recomputes xp from xv (= x(t+2)) and reloads xv.
    auto estep = [&](int rb, ull xp[CH][4], ull xv[CH][4], int tload) {
        float hh[CH];
        #pragma unroll
        for (int u = 0; u < CH; ++u) {
            const longlong2* hr = reinterpret_cast<const longlong2*>(&hbuf[rb][e0 + u][0]);
            longlong2 H0 = hr[0], H1 = hr[1], H2 = hr[2], H3 = hr[3];
            ull h0 = (ull)H0.x, h1 = (ull)H0.y, h2 = (ull)H1.x, h3 = (ull)H1.y,
                h4 = (ull)H2.x, h5 = (ull)H2.y, h6 = (ull)H3.x, h7 = (ull)H3.y;
            // even tree seeded from precomputed xp; odd tree fresh
            ull a0 = fma2a(whh[0][0], h0, xp[u][0]);
            ull a1 = fma2a(whh[1][0], h0, xp[u][1]);
            ull a2 = fma2a(whh[2][0], h0, xp[u][2]);
            ull a3 = fma2a(whh[3][0], h0, xp[u][3]);
            ull b0a = mul2(whh[0][1], h1), b1a = mul2(whh[1][1], h1),
                b2a = mul2(whh[2][1], h1), b3a = mul2(whh[3][1], h1);
            fma2(a0, whh[0][2], h2); fma2(a1, whh[1][2], h2);
            fma2(a2, whh[2][2], h2); fma2(a3, whh[3][2], h2);
            fma2(b0a, whh[0][3], h3); fma2(b1a, whh[1][3], h3);
            fma2(b2a, whh[2][3], h3); fma2(b3a, whh[3][3], h3);
            fma2(a0, whh[0][4], h4); fma2(a1, whh[1][4], h4);
            fma2(a2, whh[2][4], h4); fma2(a3, whh[3][4], h4);
            fma2(b0a, whh[0][5], h5); fma2(b1a, whh[1][5], h5);
            fma2(b2a, whh[2][5], h5); fma2(b3a, whh[3][5], h5);
            fma2(a0, whh[0][6], h6); fma2(a1, whh[1][6], h6);
            fma2(a2, whh[2][6], h6); fma2(a3, whh[3][6], h6);
            fma2(b0a, whh[0][7], h7); fma2(b1a, whh[1][7], h7);
            fma2(b2a, whh[2][7], h7); fma2(b3a, whh[3][7], h7);
            hh[u] = gates(add2(a0, b0a), add2(a1, b1a),
                          add2(a2, b2a), add2(a3, b3a), cs[u]);
        }
        #pragma unroll
        for (int u = 0; u < CH; ++u) hbuf[rb ^ 1][e0 + u][j] = hh[u];
        // tail filler: next-next step's x projection (h-independent FFMAs)
        xproj(xp, xv);
        if (tload < Tsz) ldx(xv, tload);
        __syncwarp();
    };

    // prologue: xpA/xpB = proj of x(0)/x(1); xv/xn = x(2)/x(3)
    ull xv[CH][4], xn[CH][4], xpA[CH][4], xpB[CH][4];
    ldx(xv, 0); ldx(xn, 1);
    xproj(xpA, xv); xproj(xpB, xn);
    ldx(xv, 2); ldx(xn, 3);

    #pragma unroll 1
    for (int t = 0; t < Tsz; t += 2) {
        estep(0, xpA, xv, t + 4);    // consumes xpA(t),   rebuilds xpA(t+2)
        estep(1, xpB, xn, t + 5);    // consumes xpB(t+1), rebuilds xpB(t+3)
    }
    // hT for both chains in hbuf[0]

    // ---------------- decoder prep ----------------
    ull xpdpk[CH][4];
    #pragma unroll
    for (int g = 0; g < 4; ++g) {
        const bool isG = (g == 2);
        const float scf = isG ? 1.0f : 0.5f;
        const int row = g * Hsz + j;
        const float bsum = scf * (dBih[row] + dBhh[row]);
        const ull* wr = reinterpret_cast<const ull*>(dWih + row * Hsz);
        #pragma unroll
        for (int u = 0; u < CH; ++u) {
            const ull* hr0 = reinterpret_cast<const ull*>(&hbuf[0][e0 + u][0]);
            ull acc = pk(bsum, 0.0f);
            #pragma unroll
            for (int p = 0; p < 8; ++p) {
                ull w = isG ? wr[p] : mul2(wr[p], scH);
                fma2(acc, w, hr0[p]);
            }
            xpdpk[u][g] = pk(redu(acc), 0.0f);
        }
        const ull* wh = reinterpret_cast<const ull*>(dWhh + row * Hsz);
        #pragma unroll
        for (int p = 0; p < 8; ++p) whh[g][p] = isG ? wh[p] : mul2(wh[p], scH);
    }
    ull owp[8];
    const int f = j & 7;
    {
        const ull* orow = reinterpret_cast<const ull*>(oW + f * Hsz);
        #pragma unroll
        for (int p = 0; p < 8; ++p) owp[p] = orow[p];
    }
    const ull outbpk = pk(oB[f], 0.0f);

    cs[0] = 0.0f; cs[1] = 0.0f;
    __syncwarp();                 // all lanes done reading hT
    #pragma unroll
    for (int u = 0; u < CH; ++u) hbuf[0][e0 + u][j] = 0.0f;
    __syncwarp();

    float* po = out + b0 * Tsz * Fsz + f;   // chain u at po[u*Tsz*Fsz]
    #define OSTRIDE (Tsz * Fsz)

    // decoder step: reads h_{t-1}; when doOut, emits output row for t-1
    // reusing the same h loads, then computes h_t.
    auto dstep = [&](int rb, bool doOut) {
        float hh[CH];
        #pragma unroll
        for (int u = 0; u < CH; ++u) {
            const longlong2* hr = reinterpret_cast<const longlong2*>(&hbuf[rb][e0 + u][0]);
            longlong2 H0 = hr[0], H1 = hr[1], H2 = hr[2], H3 = hr[3];
            ull h0 = (ull)H0.x, h1 = (ull)H0.y, h2 = (ull)H1.x, h3 = (ull)H1.y,
                h4 = (ull)H2.x, h5 = (ull)H2.y, h6 = (ull)H3.x, h7 = (ull)H3.y;
            if (doOut) {
                ull oacc = fma2a(owp[0], h0, outbpk);
                fma2(oacc, owp[1], h1); fma2(oacc, owp[2], h2);
                fma2(oacc, owp[3], h3); fma2(oacc, owp[4], h4);
                fma2(oacc, owp[5], h5); fma2(oacc, owp[6], h6);
                fma2(oacc, owp[7], h7);
                if (j < 8) po[u * OSTRIDE] = redu(oacc);
            }
            ull a0 = fma2a(whh[0][0], h0, xpdpk[u][0]);
            ull a1 = fma2a(whh[1][0], h0, xpdpk[u][1]);
            ull a2 = fma2a(whh[2][0], h0, xpdpk[u][2]);
            ull a3 = fma2a(whh[3][0], h0, xpdpk[u][3]);
            ull b0a = mul2(whh[0][1], h1), b1a = mul2(whh[1][1], h1),
                b2a = mul2(whh[2][1], h1), b3a = mul2(whh[3][1], h1);
            fma2(a0, whh[0][2], h2); fma2(a1, whh[1][2], h2);
            fma2(a2, whh[2][2], h2); fma2(a3, whh[3][2], h2);
            fma2(b0a, whh[0][3], h3); fma2(b1a, whh[1][3], h3);
            fma2(b2a, whh[2][3], h3); fma2(b3a, whh[3][3], h3);
            fma2(a0, whh[0][4], h4); fma2(a1, whh[1][4], h4);
            fma2(a2, whh[2][4], h4); fma2(a3, whh[3][4], h4);
            fma2(b0a, whh[0][5], h5); fma2(b1a, whh[1][5], h5);
            fma2(b2a, whh[2][5], h5); fma2(b3a, whh[3][5], h5);
            fma2(a0, whh[0][6], h6); fma2(a1, whh[1][6], h6);
            fma2(a2, whh[2][6], h6); fma2(a3, whh[3][6], h6);
            fma2(b0a, whh[0][7], h7); fma2(b1a, whh[1][7], h7);
            fma2(b2a, whh[2][7], h7); fma2(b3a, whh[3][7], h7);
            hh[u] = gates(add2(a0, b0a), add2(a1, b1a),
                          add2(a2, b2a), add2(a3, b3a), cs[u]);
        }
        if (doOut) po += Fsz;
        #pragma unroll
        for (int u = 0; u < CH; ++u) hbuf[rb ^ 1][e0 + u][j] = hh[u];
        __syncwarp();
    };

    dstep(0, false);   // t=0 (no previous h to emit)
    dstep(1, true);    // t=1, emits row 0
    #pragma unroll 1
    for (int t = 2; t < Tsz; t += 2) {
        dstep(0, true);
        dstep(1, true);
    }
    // emit final row (h_{511} in hbuf[0])
    #pragma unroll
    for (int u = 0; u < CH; ++u) {
        const ull* hr = reinterpret_cast<const ull*>(&hbuf[0][e0 + u][0]);
        ull oacc = fma2a(owp[0], hr[0], outbpk);
        #pragma unroll
        for (int p = 1; p < 8; ++p) fma2(oacc, owp[p], hr[p]);
        if (j < 8) po[u * OSTRIDE] = redu(oacc);
    }
}

extern "C" void kernel_launch(void* const* d_in, const int* in_sizes, int n_in,
                              void* d_out, int out_size) {
    (void)in_sizes; (void)n_in; (void)out_size;
    lstm_ae<<<Bsz / EPB, THREADS>>>(
        (const float*)d_in[0],
        (const float*)d_in[1], (const float*)d_in[2],
        (const float*)d_in[3], (const float*)d_in[4],
        (const float*)d_in[5], (const float*)d_in[6],
        (const float*)d_in[7], (const float*)d_in[8],
        (const float*)d_in[9], (const float*)d_in[10],
        (float*)d_out);
}